// round 1
// baseline (speedup 1.0000x reference)
#include <cuda_runtime.h>
#include <math.h>

// PointLoss_like_GPS — GB300 sm_103a
// inputs: d_in[0]=array1 [B,N,3] f32, d_in[1]=array2 [B,N,3] f32,
//         d_in[2]=alpha (1 f32), d_in[3]=beta (1 f32)
// output: d_out[0] = mean_b(0.5*f12 + 0.5*f21) * 100
//
// f(arr, samples) = sum_m -s_m * exp(-s_m),
//   s_m = alpha * dmin_m^beta + alpha^(-1/beta),
//   dmin_m = min_n sum_d max(|samples[m,d]-arr[n,d]|, 1e-7)

#define NPTS 4096
#define DIMS 3
#define TILE 2048          // reference points per shared tile (24 KB)
#define THREADS 256
#define EPSV 1e-7f

// scratch for per-block partial sums (deterministic two-stage reduction;
// no device allocation allowed, so this is a __device__ global)
__device__ float g_partials[1024];

__global__ void __launch_bounds__(THREADS)
gps_main_kernel(const float* __restrict__ a1,
                const float* __restrict__ a2,
                const float* __restrict__ alpha_p,
                const float* __restrict__ beta_p)
{
    __shared__ float sh[TILE * DIMS];   // 24576 B
    __shared__ float red[THREADS / 32];

    const int tid  = threadIdx.x;
    // 16 blocks per (batch, direction) pair: 4096 queries / 256 threads
    const int pair = blockIdx.x >> 4;           // [0, 2B)
    const int q    = ((blockIdx.x & 15) << 8) + tid;   // query index in [0, 4096)
    const int b    = pair >> 1;

    const float* base1 = a1 + (size_t)b * NPTS * DIMS;
    const float* base2 = a2 + (size_t)b * NPTS * DIMS;
    // pair&1 == 0 : f12 -> samples = array2[b], refs = array1[b]
    // pair&1 == 1 : f21 -> samples = array1[b], refs = array2[b]
    const float* samples = (pair & 1) ? base1 : base2;
    const float* refs    = (pair & 1) ? base2 : base1;

    const float qx = samples[q * 3 + 0];
    const float qy = samples[q * 3 + 1];
    const float qz = samples[q * 3 + 2];

    float dmin = 3.402823466e38f;

    for (int t = 0; t < NPTS; t += TILE) {
        __syncthreads();
        // cooperative tile load: TILE*3 = 6144 floats = 1536 float4
        const float4* src = (const float4*)(refs + (size_t)t * DIMS);
        float4* dst = (float4*)sh;
        #pragma unroll
        for (int i = 0; i < (TILE * DIMS / 4) / THREADS; i++)
            dst[tid + i * THREADS] = src[tid + i * THREADS];
        __syncthreads();

        // warp-uniform shared reads -> conflict-free broadcast
        #pragma unroll 8
        for (int j = 0; j < TILE; j++) {
            float dx = fmaxf(fabsf(qx - sh[j * 3 + 0]), EPSV);
            float dy = fmaxf(fabsf(qy - sh[j * 3 + 1]), EPSV);
            float dz = fmaxf(fabsf(qz - sh[j * 3 + 2]), EPSV);
            dmin = fminf(dmin, dx + dy + dz);
        }
    }

    const float alpha = *alpha_p;
    const float beta  = *beta_p;
    const float delta = powf(alpha, -1.0f / beta);
    const float s = alpha * powf(dmin, beta) + delta;
    float v = -s * expf(-s);

    // deterministic block reduction
    #pragma unroll
    for (int o = 16; o > 0; o >>= 1)
        v += __shfl_down_sync(0xffffffffu, v, o);
    if ((tid & 31) == 0) red[tid >> 5] = v;
    __syncthreads();
    if (tid < (THREADS / 32)) {
        v = red[tid];
        #pragma unroll
        for (int o = (THREADS / 64); o > 0; o >>= 1)
            v += __shfl_down_sync(0xffu, v, o);
        if (tid == 0) g_partials[blockIdx.x] = v;
    }
}

__global__ void gps_final_kernel(float* __restrict__ out, int nblocks, float scale)
{
    __shared__ float red[4];
    const int tid = threadIdx.x;   // 128 threads
    float v = (tid < nblocks) ? g_partials[tid] : 0.0f;
    #pragma unroll
    for (int o = 16; o > 0; o >>= 1)
        v += __shfl_down_sync(0xffffffffu, v, o);
    if ((tid & 31) == 0) red[tid >> 5] = v;
    __syncthreads();
    if (tid == 0)
        out[0] = (red[0] + red[1] + red[2] + red[3]) * scale;
}

extern "C" void kernel_launch(void* const* d_in, const int* in_sizes, int n_in,
                              void* d_out, int out_size)
{
    const float* a1    = (const float*)d_in[0];
    const float* a2    = (const float*)d_in[1];
    const float* alpha = (const float*)d_in[2];
    const float* beta  = (const float*)d_in[3];
    float* out = (float*)d_out;

    const int B = in_sizes[0] / (NPTS * DIMS);      // B*N*D elements
    const int nblocks = 2 * B * (NPTS / THREADS);   // 16 blocks per (b,dir) pair

    gps_main_kernel<<<nblocks, THREADS>>>(a1, a2, alpha, beta);

    // result = mean_b(0.5*(f12+f21)) * 100 = (50/B) * sum of all partials
    const float scale = 50.0f / (float)B;
    gps_final_kernel<<<1, 128>>>(out, nblocks, scale);
}

// round 2
// speedup vs baseline: 1.3425x; 1.3425x over previous
#include <cuda_runtime.h>
#include <math.h>
#include <stdint.h>

// PointLoss_like_GPS — GB300 sm_103a, Round 2
// f32x2-packed L1 nearest-neighbor + abs-modifier FADDs, SoA shared tiles.

#define NPTS 4096
#define DIMS 3
#define TILE 2048
#define THREADS 256

__device__ float g_partials[1024];

// add.rn.f32x2: packed (a.lo+b.lo, a.hi+b.hi); results returned as two floats.
// ptxas allocates the .b64 temp as a register pair, so the mov.b64 unpack is free.
__device__ __forceinline__ float2 addf32x2(unsigned long long a, unsigned long long b)
{
    float2 r;
    asm("{\n\t"
        ".reg .b64 t;\n\t"
        "add.rn.f32x2 t, %2, %3;\n\t"
        "mov.b64 {%0, %1}, t;\n\t"
        "}"
        : "=f"(r.x), "=f"(r.y) : "l"(a), "l"(b));
    return r;
}

__device__ __forceinline__ unsigned long long bcast2(float v)
{
    unsigned long long r;
    asm("mov.b64 %0, {%1, %1};" : "=l"(r) : "f"(v));
    return r;
}

__global__ void __launch_bounds__(THREADS)
gps_main_kernel(const float* __restrict__ a1,
                const float* __restrict__ a2,
                const float* __restrict__ alpha_p,
                const float* __restrict__ beta_p)
{
    __shared__ __align__(16) float shX[TILE];
    __shared__ __align__(16) float shY[TILE];
    __shared__ __align__(16) float shZ[TILE];
    __shared__ float red[THREADS / 32];

    const int tid  = threadIdx.x;
    const int pair = blockIdx.x >> 4;                 // [0, 2B)
    const int q    = ((blockIdx.x & 15) << 8) + tid;  // [0, 4096)
    const int b    = pair >> 1;

    const float* base1 = a1 + (size_t)b * NPTS * DIMS;
    const float* base2 = a2 + (size_t)b * NPTS * DIMS;
    const float* samples = (pair & 1) ? base1 : base2;
    const float* refs    = (pair & 1) ? base2 : base1;

    const float qx = samples[q * 3 + 0];
    const float qy = samples[q * 3 + 1];
    const float qz = samples[q * 3 + 2];

    // packed negated query coords for f32x2 subtraction: d = ref + (-q)
    const unsigned long long nqx2 = bcast2(-qx);
    const unsigned long long nqy2 = bcast2(-qy);
    const unsigned long long nqz2 = bcast2(-qz);

    float dm0 = 3.402823466e38f, dm1 = dm0, dm2 = dm0, dm3 = dm0;

    for (int t = 0; t < NPTS; t += TILE) {
        __syncthreads();
        // AoS -> SoA transpose into shared (one-time cost per tile)
        #pragma unroll
        for (int i = 0; i < TILE / THREADS; i++) {
            const int idx = tid + i * THREADS;
            const float* p = refs + (size_t)(t + idx) * 3;
            shX[idx] = p[0];
            shY[idx] = p[1];
            shZ[idx] = p[2];
        }
        __syncthreads();

        const double2* X = (const double2*)shX;   // LDS.128 -> two natural f32x2 pairs
        const double2* Y = (const double2*)shY;
        const double2* Z = (const double2*)shZ;

        #pragma unroll 4
        for (int j = 0; j < TILE / 4; j++) {
            const double2 xv = X[j], yv = Y[j], zv = Z[j];

            const float2 dx01 = addf32x2(__double_as_longlong(xv.x), nqx2);
            const float2 dx23 = addf32x2(__double_as_longlong(xv.y), nqx2);
            const float2 dy01 = addf32x2(__double_as_longlong(yv.x), nqy2);
            const float2 dy23 = addf32x2(__double_as_longlong(yv.y), nqy2);
            const float2 dz01 = addf32x2(__double_as_longlong(zv.x), nqz2);
            const float2 dz23 = addf32x2(__double_as_longlong(zv.y), nqz2);

            // |dx|+|dy| folds abs into FADD operand modifiers
            const float s0 = (fabsf(dx01.x) + fabsf(dy01.x)) + fabsf(dz01.x);
            const float s1 = (fabsf(dx01.y) + fabsf(dy01.y)) + fabsf(dz01.y);
            const float s2 = (fabsf(dx23.x) + fabsf(dy23.x)) + fabsf(dz23.x);
            const float s3 = (fabsf(dx23.y) + fabsf(dy23.y)) + fabsf(dz23.y);

            dm0 = fminf(dm0, s0);
            dm1 = fminf(dm1, s1);
            dm2 = fminf(dm2, s2);
            dm3 = fminf(dm3, s3);
        }
    }

    const float dmin = fminf(fminf(dm0, dm1), fminf(dm2, dm3));

    const float alpha = *alpha_p;
    const float beta  = *beta_p;
    const float delta = powf(alpha, -1.0f / beta);
    const float s = alpha * powf(dmin, beta) + delta;
    float v = -s * expf(-s);

    #pragma unroll
    for (int o = 16; o > 0; o >>= 1)
        v += __shfl_down_sync(0xffffffffu, v, o);
    if ((tid & 31) == 0) red[tid >> 5] = v;
    __syncthreads();
    if (tid < (THREADS / 32)) {
        v = red[tid];
        #pragma unroll
        for (int o = (THREADS / 64); o > 0; o >>= 1)
            v += __shfl_down_sync(0xffu, v, o);
        if (tid == 0) g_partials[blockIdx.x] = v;
    }
}

__global__ void gps_final_kernel(float* __restrict__ out, int nblocks, float scale)
{
    __shared__ float red[4];
    const int tid = threadIdx.x;   // 128 threads
    float v = (tid < nblocks) ? g_partials[tid] : 0.0f;
    #pragma unroll
    for (int o = 16; o > 0; o >>= 1)
        v += __shfl_down_sync(0xffffffffu, v, o);
    if ((tid & 31) == 0) red[tid >> 5] = v;
    __syncthreads();
    if (tid == 0)
        out[0] = (red[0] + red[1] + red[2] + red[3]) * scale;
}

extern "C" void kernel_launch(void* const* d_in, const int* in_sizes, int n_in,
                              void* d_out, int out_size)
{
    const float* a1    = (const float*)d_in[0];
    const float* a2    = (const float*)d_in[1];
    const float* alpha = (const float*)d_in[2];
    const float* beta  = (const float*)d_in[3];
    float* out = (float*)d_out;

    const int B = in_sizes[0] / (NPTS * DIMS);
    const int nblocks = 2 * B * (NPTS / THREADS);

    gps_main_kernel<<<nblocks, THREADS>>>(a1, a2, alpha, beta);

    const float scale = 50.0f / (float)B;
    gps_final_kernel<<<1, 128>>>(out, nblocks, scale);
}

// round 3
// speedup vs baseline: 1.6508x; 1.2296x over previous
#include <cuda_runtime.h>
#include <math.h>
#include <stdint.h>

// PointLoss_like_GPS — GB300 sm_103a, Round 3
// Ref-split grid (512 blocks) for occupancy + fused last-block finalization.

#define NPTS 4096
#define DIMS 3
#define THREADS 256
#define SPLITS 4
#define RSPLIT (NPTS / SPLITS)        // 1024 refs per block
#define MAXQ 32768                    // 2B * 4096 at B=4

__device__ float g_dmin[SPLITS * MAXQ];   // per-(split, query) partial min
__device__ float g_partials[256];         // per-final-block partial sums
__device__ unsigned int g_ticket;         // last-block ticket (reset by main k)

__device__ __forceinline__ float2 addf32x2(unsigned long long a, unsigned long long b)
{
    float2 r;
    asm("{\n\t"
        ".reg .b64 t;\n\t"
        "add.rn.f32x2 t, %2, %3;\n\t"
        "mov.b64 {%0, %1}, t;\n\t"
        "}"
        : "=f"(r.x), "=f"(r.y) : "l"(a), "l"(b));
    return r;
}

__device__ __forceinline__ unsigned long long bcast2(float v)
{
    unsigned long long r;
    asm("mov.b64 %0, {%1, %1};" : "=l"(r) : "f"(v));
    return r;
}

__global__ void __launch_bounds__(THREADS)
gps_main_kernel(const float* __restrict__ a1,
                const float* __restrict__ a2)
{
    __shared__ __align__(16) float shX[RSPLIT];
    __shared__ __align__(16) float shY[RSPLIT];
    __shared__ __align__(16) float shZ[RSPLIT];

    const int tid = threadIdx.x;
    const int bx  = blockIdx.x;
    if (bx == 0 && tid == 0) g_ticket = 0;   // reset for the stream-ordered finalize

    // bx = pair * (16*SPLITS) + qc * SPLITS + sp
    const int sp   = bx & (SPLITS - 1);
    const int qc   = (bx >> 2) & 15;
    const int pair = bx >> 6;                 // [0, 2B)
    const int q    = (qc << 8) + tid;         // [0, 4096)
    const int b    = pair >> 1;

    const float* base1 = a1 + (size_t)b * NPTS * DIMS;
    const float* base2 = a2 + (size_t)b * NPTS * DIMS;
    const float* samples = (pair & 1) ? base1 : base2;
    const float* refs    = ((pair & 1) ? base2 : base1) + (size_t)sp * RSPLIT * DIMS;

    const float qx = samples[q * 3 + 0];
    const float qy = samples[q * 3 + 1];
    const float qz = samples[q * 3 + 2];

    const unsigned long long nqx2 = bcast2(-qx);
    const unsigned long long nqy2 = bcast2(-qy);
    const unsigned long long nqz2 = bcast2(-qz);

    // AoS -> SoA tile load (1024 points, 12 floats per thread)
    #pragma unroll
    for (int i = 0; i < RSPLIT / THREADS; i++) {
        const int idx = tid + i * THREADS;
        const float* p = refs + (size_t)idx * 3;
        shX[idx] = p[0];
        shY[idx] = p[1];
        shZ[idx] = p[2];
    }
    __syncthreads();

    float dm0 = 3.402823466e38f, dm1 = dm0, dm2 = dm0, dm3 = dm0;

    const double2* X = (const double2*)shX;
    const double2* Y = (const double2*)shY;
    const double2* Z = (const double2*)shZ;

    #pragma unroll 8
    for (int j = 0; j < RSPLIT / 4; j++) {
        const double2 xv = X[j], yv = Y[j], zv = Z[j];

        const float2 dx01 = addf32x2(__double_as_longlong(xv.x), nqx2);
        const float2 dx23 = addf32x2(__double_as_longlong(xv.y), nqx2);
        const float2 dy01 = addf32x2(__double_as_longlong(yv.x), nqy2);
        const float2 dy23 = addf32x2(__double_as_longlong(yv.y), nqy2);
        const float2 dz01 = addf32x2(__double_as_longlong(zv.x), nqz2);
        const float2 dz23 = addf32x2(__double_as_longlong(zv.y), nqz2);

        const float s0 = (fabsf(dx01.x) + fabsf(dy01.x)) + fabsf(dz01.x);
        const float s1 = (fabsf(dx01.y) + fabsf(dy01.y)) + fabsf(dz01.y);
        const float s2 = (fabsf(dx23.x) + fabsf(dy23.x)) + fabsf(dz23.x);
        const float s3 = (fabsf(dx23.y) + fabsf(dy23.y)) + fabsf(dz23.y);

        dm0 = fminf(dm0, s0);
        dm1 = fminf(dm1, s1);
        dm2 = fminf(dm2, s2);
        dm3 = fminf(dm3, s3);
    }

    const float dmin = fminf(fminf(dm0, dm1), fminf(dm2, dm3));
    g_dmin[sp * MAXQ + pair * NPTS + q] = dmin;
}

// Finalize: min over splits, epilogue math, two-level deterministic reduction,
// last block writes the scalar output.
__global__ void __launch_bounds__(THREADS)
gps_finalize_kernel(float* __restrict__ out,
                    const float* __restrict__ alpha_p,
                    const float* __restrict__ beta_p,
                    int nq, float scale)
{
    __shared__ float red[THREADS / 32];
    __shared__ bool isLast;

    const int tid = threadIdx.x;
    const int gq  = blockIdx.x * THREADS + tid;

    float dmin = 3.402823466e38f;
    #pragma unroll
    for (int s = 0; s < SPLITS; s++)
        dmin = fminf(dmin, g_dmin[s * MAXQ + gq]);

    const float alpha = *alpha_p;
    const float beta  = *beta_p;
    const float delta = powf(alpha, -1.0f / beta);
    const float sv = alpha * powf(dmin, beta) + delta;
    float v = -sv * expf(-sv);

    #pragma unroll
    for (int o = 16; o > 0; o >>= 1)
        v += __shfl_down_sync(0xffffffffu, v, o);
    if ((tid & 31) == 0) red[tid >> 5] = v;
    __syncthreads();
    if (tid < (THREADS / 32)) {
        v = red[tid];
        #pragma unroll
        for (int o = (THREADS / 64); o > 0; o >>= 1)
            v += __shfl_down_sync(0xffu, v, o);
        if (tid == 0) {
            g_partials[blockIdx.x] = v;
            __threadfence();
            const unsigned int t = atomicAdd(&g_ticket, 1u);
            isLast = (t == gridDim.x - 1);
        }
    }
    __syncthreads();

    if (isLast && tid < 32) {
        const int nblk = gridDim.x;
        float acc = 0.0f;
        for (int i = tid; i < nblk; i += 32)
            acc += *((volatile float*)&g_partials[i]);
        #pragma unroll
        for (int o = 16; o > 0; o >>= 1)
            acc += __shfl_down_sync(0xffffffffu, acc, o);
        if (tid == 0)
            out[0] = acc * scale;
    }
}

extern "C" void kernel_launch(void* const* d_in, const int* in_sizes, int n_in,
                              void* d_out, int out_size)
{
    const float* a1    = (const float*)d_in[0];
    const float* a2    = (const float*)d_in[1];
    const float* alpha = (const float*)d_in[2];
    const float* beta  = (const float*)d_in[3];
    float* out = (float*)d_out;

    const int B  = in_sizes[0] / (NPTS * DIMS);
    const int nq = 2 * B * NPTS;                         // total queries
    const int main_blocks = 2 * B * 16 * SPLITS;          // 512 at B=4
    const int fin_blocks  = nq / THREADS;                 // 128 at B=4

    gps_main_kernel<<<main_blocks, THREADS>>>(a1, a2);

    const float scale = 50.0f / (float)B;
    gps_finalize_kernel<<<fin_blocks, THREADS>>>(out, alpha, beta, nq, scale);
}